// round 7
// baseline (speedup 1.0000x reference)
#include <cuda_runtime.h>

#define N_NODES 100000
#define N_EDGES 1000000
#define F_IN 15
#define H 64
#define EMB 128
#define NREL 13
#define NB 4

// ---------------- scratch (no allocations allowed) ----------------
__device__ float g_A[N_NODES * H];          // 25.6 MB
__device__ float g_B[N_NODES * H];          // 25.6 MB
__device__ float g_Z[N_NODES * H * NB];     // 102.4 MB
__device__ float g_psum[256 * H];
__device__ float g_pmax[256 * H];

// ---------------- input projection: h0 = nf @ W_in + b_in ----------------
__global__ void k_inproj(const float* __restrict__ nf, const float* __restrict__ W,
                         const float* __restrict__ b, float* __restrict__ out) {
    __shared__ float sW[F_IN * H];
    __shared__ float sb[H];
    __shared__ float snf[4 * F_IN];
    int tid = threadIdx.x;
    for (int i = tid; i < F_IN * H; i += 256) sW[i] = W[i];
    if (tid < H) sb[tid] = b[tid];
    int n0 = blockIdx.x * 4;
    if (tid < 4 * F_IN) {
        int g = n0 * F_IN + tid;
        snf[tid] = (g < N_NODES * F_IN) ? nf[g] : 0.f;
    }
    __syncthreads();
    int lr = tid >> 6, col = tid & 63;
    int node = n0 + lr;
    if (node < N_NODES) {
        float acc = sb[col];
#pragma unroll
        for (int k = 0; k < F_IN; k++) acc = fmaf(snf[lr * F_IN + k], sW[k * H + col], acc);
        out[node * H + col] = acc;
    }
}

// ---------------- per-layer dense prep ----------------
// acc = act(hin) @ Wself + bself          (self-term, also the scatter accumulator)
// z[:,b,:] = act(hin) @ bases[b]          for b = 0..3
__global__ void k_prep(const float* __restrict__ hin, int relu_in,
                       const float* __restrict__ Wself, const float* __restrict__ bself,
                       const float* __restrict__ bases,
                       float* __restrict__ acc, float* __restrict__ z) {
    __shared__ float sA[H][68];   // transposed: sA[k][row]
    __shared__ float sB[H][68];   // sB[k][col]
    int tid = threadIdx.x;
    int n0 = blockIdx.x * 64;

    for (int i = tid; i < H * H; i += 256) {
        int row = i >> 6, k = i & 63;
        int node = n0 + row;
        float v = (node < N_NODES) ? hin[node * H + k] : 0.f;
        if (relu_in) v = fmaxf(v, 0.f);
        sA[k][row] = v;
    }

    int tx = tid & 15, ty = tid >> 4;

    for (int m = 0; m < 5; m++) {
        const float* Bsrc = (m == 0) ? Wself : (bases + (m - 1) * H * H);
        for (int i = tid; i < H * H; i += 256) sB[i >> 6][i & 63] = Bsrc[i];
        __syncthreads();

        float c[4][4] = {};
#pragma unroll
        for (int k = 0; k < H; k++) {
            float4 a4 = *(const float4*)&sA[k][ty * 4];
            float4 b4 = *(const float4*)&sB[k][tx * 4];
            float av[4] = {a4.x, a4.y, a4.z, a4.w};
            float bv[4] = {b4.x, b4.y, b4.z, b4.w};
#pragma unroll
            for (int i = 0; i < 4; i++)
#pragma unroll
                for (int j = 0; j < 4; j++)
                    c[i][j] = fmaf(av[i], bv[j], c[i][j]);
        }

        int colbase = tx * 4;
        if (m == 0) {
            float4 bsv = *(const float4*)&bself[colbase];
#pragma unroll
            for (int i = 0; i < 4; i++) {
                int node = n0 + ty * 4 + i;
                if (node < N_NODES) {
                    float4 o = {c[i][0] + bsv.x, c[i][1] + bsv.y,
                                c[i][2] + bsv.z, c[i][3] + bsv.w};
                    *(float4*)&acc[node * H + colbase] = o;
                }
            }
        } else {
#pragma unroll
            for (int i = 0; i < 4; i++) {
                int node = n0 + ty * 4 + i;
                if (node < N_NODES) {
                    float4 o = {c[i][0], c[i][1], c[i][2], c[i][3]};
                    *(float4*)&z[node * (H * NB) + (m - 1) * H + colbase] = o;
                }
            }
        }
        __syncthreads();   // protect sB before next overwrite
    }
}

// ---------------- edge scatter: acc[tgt] += sum_b coeffs[etype,b] * z[src,b,:] ----------------
__global__ void k_edges(const int* __restrict__ src, const int* __restrict__ tgt,
                        const int* __restrict__ et, const float* __restrict__ coeffs,
                        const float* __restrict__ z, float* __restrict__ acc) {
    int tid = threadIdx.x;
    int lane = tid & 63;
    int e = blockIdx.x * 4 + (tid >> 6);
    if (e >= N_EDGES) return;
    int s = __ldg(&src[e]);
    int t = __ldg(&tgt[e]);
    int r = __ldg(&et[e]);
    float c0 = __ldg(&coeffs[r * NB + 0]);
    float c1 = __ldg(&coeffs[r * NB + 1]);
    float c2 = __ldg(&coeffs[r * NB + 2]);
    float c3 = __ldg(&coeffs[r * NB + 3]);
    const float* zs = z + s * (H * NB);
    float m = c0 * __ldg(&zs[lane])
            + c1 * __ldg(&zs[H + lane])
            + c2 * __ldg(&zs[2 * H + lane])
            + c3 * __ldg(&zs[3 * H + lane]);
    atomicAdd(&acc[t * H + lane], m);
}

// ---------------- pooling stage 1: per-block partial mean/max of relu(h) ----------------
__global__ void k_pool1(const float* __restrict__ hbuf) {
    int tid = threadIdx.x;
    int col = tid & 63;
    int sub = tid >> 6;   // 0..3
    float s = 0.f, mx = -3.4e38f;
    for (int n = blockIdx.x * 4 + sub; n < N_NODES; n += gridDim.x * 4) {
        float v = fmaxf(hbuf[n * H + col], 0.f);
        s += v;
        mx = fmaxf(mx, v);
    }
    __shared__ float ss[256], sm[256];
    ss[tid] = s; sm[tid] = mx;
    __syncthreads();
    if (sub == 0) {
        float fs = ss[col] + ss[64 + col] + ss[128 + col] + ss[192 + col];
        float fm = fmaxf(fmaxf(sm[col], sm[64 + col]), fmaxf(sm[128 + col], sm[192 + col]));
        g_psum[blockIdx.x * H + col] = fs;
        g_pmax[blockIdx.x * H + col] = fm;
    }
}

// ---------------- pooling stage 2 + readout MLP -> graph_emb ----------------
__global__ void k_pool2(const float* __restrict__ Wr1, const float* __restrict__ br1,
                        const float* __restrict__ Wr2, const float* __restrict__ br2,
                        float* __restrict__ out, int nblocks) {
    __shared__ float g[2 * H];
    __shared__ float t[H];
    int tid = threadIdx.x;
    if (tid < H) {
        float s = 0.f, mx = -3.4e38f;
        for (int b = 0; b < nblocks; b++) {
            s += g_psum[b * H + tid];
            mx = fmaxf(mx, g_pmax[b * H + tid]);
        }
        g[tid] = s / (float)N_NODES;
        g[H + tid] = mx;
    }
    __syncthreads();
    if (tid < H) {
        float a = br1[tid];
#pragma unroll 8
        for (int i = 0; i < 2 * H; i++) a = fmaf(g[i], Wr1[i * H + tid], a);
        t[tid] = fmaxf(a, 0.f);
    }
    __syncthreads();
    if (tid < EMB) {
        float a = br2[tid];
#pragma unroll 8
        for (int j = 0; j < H; j++) a = fmaf(t[j], Wr2[j * EMB + tid], a);
        out[tid] = a;
    }
}

// ---------------- node embedding: out = relu(h) @ Wnp + bnp ----------------
__global__ void k_nodeemb(const float* __restrict__ hbuf, const float* __restrict__ Wnp,
                          const float* __restrict__ bnp, float* __restrict__ out) {
    __shared__ float sA[H][68];
    __shared__ float sB[H][68];
    int tid = threadIdx.x;
    int n0 = blockIdx.x * 64;

    for (int i = tid; i < H * H; i += 256) {
        int row = i >> 6, k = i & 63;
        int node = n0 + row;
        float v = (node < N_NODES) ? fmaxf(hbuf[node * H + k], 0.f) : 0.f;
        sA[k][row] = v;
    }

    int tx = tid & 15, ty = tid >> 4;

    for (int m = 0; m < 2; m++) {
        for (int i = tid; i < H * H; i += 256) {
            int k = i >> 6, col = i & 63;
            sB[k][col] = Wnp[k * EMB + m * H + col];
        }
        __syncthreads();

        float c[4][4] = {};
#pragma unroll
        for (int k = 0; k < H; k++) {
            float4 a4 = *(const float4*)&sA[k][ty * 4];
            float4 b4 = *(const float4*)&sB[k][tx * 4];
            float av[4] = {a4.x, a4.y, a4.z, a4.w};
            float bv[4] = {b4.x, b4.y, b4.z, b4.w};
#pragma unroll
            for (int i = 0; i < 4; i++)
#pragma unroll
                for (int j = 0; j < 4; j++)
                    c[i][j] = fmaf(av[i], bv[j], c[i][j]);
        }

        int colbase = tx * 4;
        float4 bv4 = *(const float4*)&bnp[m * H + colbase];
#pragma unroll
        for (int i = 0; i < 4; i++) {
            int node = n0 + ty * 4 + i;
            if (node < N_NODES) {
                float4 o = {c[i][0] + bv4.x, c[i][1] + bv4.y,
                            c[i][2] + bv4.z, c[i][3] + bv4.w};
                *(float4*)&out[node * EMB + m * H + colbase] = o;
            }
        }
        __syncthreads();
    }
}

// ---------------- launch ----------------
extern "C" void kernel_launch(void* const* d_in, const int* in_sizes, int n_in,
                              void* d_out, int out_size) {
    const float* nf     = (const float*)d_in[0];
    const int*   ei     = (const int*)  d_in[1];
    const int*   et     = (const int*)  d_in[2];
    const float* W_in   = (const float*)d_in[3];
    const float* b_in   = (const float*)d_in[4];
    const float* Wself0 = (const float*)d_in[5];
    const float* bself0 = (const float*)d_in[6];
    const float* bases0 = (const float*)d_in[7];
    const float* coeffs0= (const float*)d_in[8];
    const float* Wself1 = (const float*)d_in[9];
    const float* bself1 = (const float*)d_in[10];
    const float* bases1 = (const float*)d_in[11];
    const float* coeffs1= (const float*)d_in[12];
    const float* Wr1    = (const float*)d_in[13];
    const float* br1    = (const float*)d_in[14];
    const float* Wr2    = (const float*)d_in[15];
    const float* br2    = (const float*)d_in[16];
    const float* Wnp    = (const float*)d_in[17];
    const float* bnp    = (const float*)d_in[18];
    float* out = (float*)d_out;

    float *A, *B, *Z;
    cudaGetSymbolAddress((void**)&A, g_A);
    cudaGetSymbolAddress((void**)&B, g_B);
    cudaGetSymbolAddress((void**)&Z, g_Z);

    const int* src = ei;
    const int* tgt = ei + N_EDGES;

    int nb64 = (N_NODES + 63) / 64;

    // h0 = nf @ W_in + b_in                     -> A
    k_inproj<<<(N_NODES + 3) / 4, 256>>>(nf, W_in, b_in, A);

    // layer 0: B = A@Wself0+b ; Z = A@bases0 ; edges scatter into B
    k_prep<<<nb64, 256>>>(A, 0, Wself0, bself0, bases0, B, Z);
    k_edges<<<(N_EDGES + 3) / 4, 256>>>(src, tgt, et, coeffs0, Z, B);

    // layer 1: A = relu(B)@Wself1+b ; Z = relu(B)@bases1 ; edges scatter into A
    k_prep<<<nb64, 256>>>(B, 1, Wself1, bself1, bases1, A, Z);
    k_edges<<<(N_EDGES + 3) / 4, 256>>>(src, tgt, et, coeffs1, Z, A);

    // readout: graph_emb = out[0:128]
    k_pool1<<<256, 256>>>(A);
    k_pool2<<<1, 128>>>(Wr1, br1, Wr2, br2, out, 256);

    // node_emb = out[128:]
    k_nodeemb<<<nb64, 256>>>(A, Wnp, bnp, out + EMB);
}

// round 9
// speedup vs baseline: 1.0618x; 1.0618x over previous
#include <cuda_runtime.h>

#define N_NODES 100000
#define N_EDGES 1000000
#define F_IN 15
#define H 64
#define EMB 128
#define NREL 13
#define NB 4

// ---------------- scratch (no allocations allowed) ----------------
__device__ float g_A[N_NODES * H];          // 25.6 MB
__device__ float g_B[N_NODES * H];          // 25.6 MB
__device__ float g_Z[N_NODES * H * NB];     // 102.4 MB
__device__ float g_psum[256 * H];
__device__ float g_pmax[256 * H];
__device__ int   g_cnt[N_NODES];
__device__ int   g_row[N_NODES];
__device__ int   g_cur[N_NODES];
__device__ int   g_elist[N_EDGES];          // packed: src | (etype<<17)

// ---------------- CSR build ----------------
__global__ void k_zero(int* __restrict__ cnt) {
    int i = blockIdx.x * 256 + threadIdx.x;
    if (i < N_NODES) cnt[i] = 0;
}

__global__ void k_hist(const int* __restrict__ tgt, int* __restrict__ cnt) {
    int e = blockIdx.x * 256 + threadIdx.x;
    if (e < N_EDGES) atomicAdd(&cnt[tgt[e]], 1);
}

// single-block exclusive scan of counts -> row/cur
__global__ void k_scan(const int* __restrict__ cnt, int* __restrict__ row,
                       int* __restrict__ cur) {
    const int CH = (N_NODES + 1023) / 1024;   // 98
    __shared__ int sp[1024];
    int tid = threadIdx.x;
    int start = tid * CH;
    int s = 0;
    for (int i = 0; i < CH; i++) {
        int idx = start + i;
        if (idx < N_NODES) s += cnt[idx];
    }
    sp[tid] = s;
    __syncthreads();
    for (int off = 1; off < 1024; off <<= 1) {
        int v = 0;
        if (tid >= off) v = sp[tid - off];
        __syncthreads();
        if (tid >= off) sp[tid] += v;
        __syncthreads();
    }
    int run = (tid == 0) ? 0 : sp[tid - 1];
    for (int i = 0; i < CH; i++) {
        int idx = start + i;
        if (idx < N_NODES) {
            row[idx] = run;
            cur[idx] = run;
            run += cnt[idx];
        }
    }
}

__global__ void k_scatter(const int* __restrict__ src, const int* __restrict__ tgt,
                          const int* __restrict__ et, int* __restrict__ cur,
                          int* __restrict__ elist) {
    int e = blockIdx.x * 256 + threadIdx.x;
    if (e >= N_EDGES) return;
    int t = tgt[e];
    int pos = atomicAdd(&cur[t], 1);
    elist[pos] = src[e] | (et[e] << 17);
}

// ---------------- input projection: h0 = nf @ W_in + b_in ----------------
__global__ void k_inproj(const float* __restrict__ nf, const float* __restrict__ W,
                         const float* __restrict__ b, float* __restrict__ out) {
    __shared__ float sW[F_IN * H];
    __shared__ float sb[H];
    __shared__ float snf[4 * F_IN];
    int tid = threadIdx.x;
    for (int i = tid; i < F_IN * H; i += 256) sW[i] = W[i];
    if (tid < H) sb[tid] = b[tid];
    int n0 = blockIdx.x * 4;
    if (tid < 4 * F_IN) {
        int g = n0 * F_IN + tid;
        snf[tid] = (g < N_NODES * F_IN) ? nf[g] : 0.f;
    }
    __syncthreads();
    int lr = tid >> 6, col = tid & 63;
    int node = n0 + lr;
    if (node < N_NODES) {
        float acc = sb[col];
#pragma unroll
        for (int k = 0; k < F_IN; k++) acc = fmaf(snf[lr * F_IN + k], sW[k * H + col], acc);
        out[node * H + col] = acc;
    }
}

// ---------------- per-layer dense prep (128-node tile, 8x4 microtile) ----------------
// acc = act(hin) @ Wself + bself ; z[:,b,:] = act(hin) @ bases[b]
__global__ void k_prep(const float* __restrict__ hin, int relu_in,
                       const float* __restrict__ Wself, const float* __restrict__ bself,
                       const float* __restrict__ bases,
                       float* __restrict__ acc, float* __restrict__ z) {
    __shared__ float sA[H][132];   // transposed: sA[k][row], 128 rows
    __shared__ float sB[H][68];    // sB[k][col]
    int tid = threadIdx.x;         // 256
    int n0 = blockIdx.x * 128;

    for (int i = tid; i < 128 * H; i += 256) {
        int row = i >> 6, k = i & 63;
        int node = n0 + row;
        float v = (node < N_NODES) ? hin[node * H + k] : 0.f;
        if (relu_in) v = fmaxf(v, 0.f);
        sA[k][row] = v;
    }

    int tx = tid & 15, ty = tid >> 4;   // 16 col-groups x4, 16 row-groups x8

    for (int m = 0; m < 5; m++) {
        const float* Bsrc = (m == 0) ? Wself : (bases + (m - 1) * H * H);
        for (int i = tid; i < H * H; i += 256) sB[i >> 6][i & 63] = Bsrc[i];
        __syncthreads();

        float c[8][4] = {};
#pragma unroll 8
        for (int k = 0; k < H; k++) {
            float4 a0 = *(const float4*)&sA[k][ty * 8];
            float4 a1 = *(const float4*)&sA[k][ty * 8 + 4];
            float4 b4 = *(const float4*)&sB[k][tx * 4];
            float av[8] = {a0.x, a0.y, a0.z, a0.w, a1.x, a1.y, a1.z, a1.w};
            float bv[4] = {b4.x, b4.y, b4.z, b4.w};
#pragma unroll
            for (int i = 0; i < 8; i++)
#pragma unroll
                for (int j = 0; j < 4; j++)
                    c[i][j] = fmaf(av[i], bv[j], c[i][j]);
        }

        int colbase = tx * 4;
        if (m == 0) {
            float4 bsv = *(const float4*)&bself[colbase];
#pragma unroll
            for (int i = 0; i < 8; i++) {
                int node = n0 + ty * 8 + i;
                if (node < N_NODES) {
                    float4 o = {c[i][0] + bsv.x, c[i][1] + bsv.y,
                                c[i][2] + bsv.z, c[i][3] + bsv.w};
                    *(float4*)&acc[node * H + colbase] = o;
                }
            }
        } else {
#pragma unroll
            for (int i = 0; i < 8; i++) {
                int node = n0 + ty * 8 + i;
                if (node < N_NODES) {
                    float4 o = {c[i][0], c[i][1], c[i][2], c[i][3]};
                    *(float4*)&z[node * (H * NB) + (m - 1) * H + colbase] = o;
                }
            }
        }
        __syncthreads();
    }
}

// ---------------- CSR edge aggregation (no atomics) ----------------
// acc[t,:] += sum_{e in in(t)} sum_b coeffs[etype(e),b] * z[src(e),b,:]
__global__ void k_edges_csr(const int* __restrict__ row, const int* __restrict__ cnt,
                            const int* __restrict__ elist, const float* __restrict__ coeffs,
                            const float* __restrict__ z, float* __restrict__ acc) {
    __shared__ float sc[NREL * NB];
    int tid = threadIdx.x;
    if (tid < NREL * NB) sc[tid] = coeffs[tid];
    __syncthreads();

    int lane = tid & 63;
    int t = blockIdx.x * 4 + (tid >> 6);
    if (t >= N_NODES) return;
    int beg = __ldg(&row[t]);
    int deg = __ldg(&cnt[t]);

    float a0 = 0.f, a1 = 0.f;
    int i = 0;
    for (; i + 2 <= deg; i += 2) {
        int pkA = __ldg(&elist[beg + i]);
        int pkB = __ldg(&elist[beg + i + 1]);
        int sA_ = pkA & 0x1FFFF, rA = pkA >> 17;
        int sB_ = pkB & 0x1FFFF, rB = pkB >> 17;
        const float* zA = z + sA_ * (H * NB);
        const float* zB = z + sB_ * (H * NB);
        const float* cA = sc + rA * NB;
        const float* cB = sc + rB * NB;
        a0 += cA[0] * __ldg(&zA[lane])
            + cA[1] * __ldg(&zA[H + lane])
            + cA[2] * __ldg(&zA[2 * H + lane])
            + cA[3] * __ldg(&zA[3 * H + lane]);
        a1 += cB[0] * __ldg(&zB[lane])
            + cB[1] * __ldg(&zB[H + lane])
            + cB[2] * __ldg(&zB[2 * H + lane])
            + cB[3] * __ldg(&zB[3 * H + lane]);
    }
    if (i < deg) {
        int pk = __ldg(&elist[beg + i]);
        int s = pk & 0x1FFFF, r = pk >> 17;
        const float* zs = z + s * (H * NB);
        const float* cf = sc + r * NB;
        a0 += cf[0] * __ldg(&zs[lane])
            + cf[1] * __ldg(&zs[H + lane])
            + cf[2] * __ldg(&zs[2 * H + lane])
            + cf[3] * __ldg(&zs[3 * H + lane]);
    }
    float a = a0 + a1;
    if (deg > 0) acc[t * H + lane] += a;
}

// ---------------- pooling stage 1 ----------------
__global__ void k_pool1(const float* __restrict__ hbuf) {
    int tid = threadIdx.x;
    int col = tid & 63;
    int sub = tid >> 6;
    float s = 0.f, mx = -3.4e38f;
    for (int n = blockIdx.x * 4 + sub; n < N_NODES; n += gridDim.x * 4) {
        float v = fmaxf(hbuf[n * H + col], 0.f);
        s += v;
        mx = fmaxf(mx, v);
    }
    __shared__ float ss[256], sm[256];
    ss[tid] = s; sm[tid] = mx;
    __syncthreads();
    if (sub == 0) {
        float fs = ss[col] + ss[64 + col] + ss[128 + col] + ss[192 + col];
        float fm = fmaxf(fmaxf(sm[col], sm[64 + col]), fmaxf(sm[128 + col], sm[192 + col]));
        g_psum[blockIdx.x * H + col] = fs;
        g_pmax[blockIdx.x * H + col] = fm;
    }
}

// ---------------- pooling stage 2 + readout MLP ----------------
__global__ void k_pool2(const float* __restrict__ Wr1, const float* __restrict__ br1,
                        const float* __restrict__ Wr2, const float* __restrict__ br2,
                        float* __restrict__ out, int nblocks) {
    __shared__ float g[2 * H];
    __shared__ float t[H];
    int tid = threadIdx.x;
    if (tid < H) {
        float s = 0.f, mx = -3.4e38f;
        for (int b = 0; b < nblocks; b++) {
            s += g_psum[b * H + tid];
            mx = fmaxf(mx, g_pmax[b * H + tid]);
        }
        g[tid] = s / (float)N_NODES;
        g[H + tid] = mx;
    }
    __syncthreads();
    if (tid < H) {
        float a = br1[tid];
#pragma unroll 8
        for (int i = 0; i < 2 * H; i++) a = fmaf(g[i], Wr1[i * H + tid], a);
        t[tid] = fmaxf(a, 0.f);
    }
    __syncthreads();
    if (tid < EMB) {
        float a = br2[tid];
#pragma unroll 8
        for (int j = 0; j < H; j++) a = fmaf(t[j], Wr2[j * EMB + tid], a);
        out[tid] = a;
    }
}

// ---------------- node embedding (128-node tile, 8x4 microtile) ----------------
__global__ void k_nodeemb(const float* __restrict__ hbuf, const float* __restrict__ Wnp,
                          const float* __restrict__ bnp, float* __restrict__ out) {
    __shared__ float sA[H][132];
    __shared__ float sB[H][68];
    int tid = threadIdx.x;
    int n0 = blockIdx.x * 128;

    for (int i = tid; i < 128 * H; i += 256) {
        int row = i >> 6, k = i & 63;
        int node = n0 + row;
        sA[k][row] = (node < N_NODES) ? fmaxf(hbuf[node * H + k], 0.f) : 0.f;
    }

    int tx = tid & 15, ty = tid >> 4;

    for (int m = 0; m < 2; m++) {
        for (int i = tid; i < H * H; i += 256) {
            int k = i >> 6, col = i & 63;
            sB[k][col] = Wnp[k * EMB + m * H + col];
        }
        __syncthreads();

        float c[8][4] = {};
#pragma unroll 8
        for (int k = 0; k < H; k++) {
            float4 a0 = *(const float4*)&sA[k][ty * 8];
            float4 a1 = *(const float4*)&sA[k][ty * 8 + 4];
            float4 b4 = *(const float4*)&sB[k][tx * 4];
            float av[8] = {a0.x, a0.y, a0.z, a0.w, a1.x, a1.y, a1.z, a1.w};
            float bv[4] = {b4.x, b4.y, b4.z, b4.w};
#pragma unroll
            for (int i = 0; i < 8; i++)
#pragma unroll
                for (int j = 0; j < 4; j++)
                    c[i][j] = fmaf(av[i], bv[j], c[i][j]);
        }

        int colbase = tx * 4;
        float4 bv4 = *(const float4*)&bnp[m * H + colbase];
#pragma unroll
        for (int i = 0; i < 8; i++) {
            int node = n0 + ty * 8 + i;
            if (node < N_NODES) {
                float4 o = {c[i][0] + bv4.x, c[i][1] + bv4.y,
                            c[i][2] + bv4.z, c[i][3] + bv4.w};
                *(float4*)&out[node * EMB + m * H + colbase] = o;
            }
        }
        __syncthreads();
    }
}

// ---------------- launch ----------------
extern "C" void kernel_launch(void* const* d_in, const int* in_sizes, int n_in,
                              void* d_out, int out_size) {
    const float* nf     = (const float*)d_in[0];
    const int*   ei     = (const int*)  d_in[1];
    const int*   et     = (const int*)  d_in[2];
    const float* W_in   = (const float*)d_in[3];
    const float* b_in   = (const float*)d_in[4];
    const float* Wself0 = (const float*)d_in[5];
    const float* bself0 = (const float*)d_in[6];
    const float* bases0 = (const float*)d_in[7];
    const float* coeffs0= (const float*)d_in[8];
    const float* Wself1 = (const float*)d_in[9];
    const float* bself1 = (const float*)d_in[10];
    const float* bases1 = (const float*)d_in[11];
    const float* coeffs1= (const float*)d_in[12];
    const float* Wr1    = (const float*)d_in[13];
    const float* br1    = (const float*)d_in[14];
    const float* Wr2    = (const float*)d_in[15];
    const float* br2    = (const float*)d_in[16];
    const float* Wnp    = (const float*)d_in[17];
    const float* bnp    = (const float*)d_in[18];
    float* out = (float*)d_out;

    float *A, *B, *Z;
    int *cnt, *row, *cur, *elist;
    cudaGetSymbolAddress((void**)&A, g_A);
    cudaGetSymbolAddress((void**)&B, g_B);
    cudaGetSymbolAddress((void**)&Z, g_Z);
    cudaGetSymbolAddress((void**)&cnt, g_cnt);
    cudaGetSymbolAddress((void**)&row, g_row);
    cudaGetSymbolAddress((void**)&cur, g_cur);
    cudaGetSymbolAddress((void**)&elist, g_elist);

    const int* src = ei;
    const int* tgt = ei + N_EDGES;

    int nb128 = (N_NODES + 127) / 128;
    int nbN   = (N_NODES + 255) / 256;
    int nbE   = (N_EDGES + 255) / 256;

    // CSR build (by target)
    k_zero<<<nbN, 256>>>(cnt);
    k_hist<<<nbE, 256>>>(tgt, cnt);
    k_scan<<<1, 1024>>>(cnt, row, cur);
    k_scatter<<<nbE, 256>>>(src, tgt, et, cur, elist);

    // h0 = nf @ W_in + b_in                     -> A
    k_inproj<<<(N_NODES + 3) / 4, 256>>>(nf, W_in, b_in, A);

    // layer 0: B = A@Wself0+b ; Z = A@bases0 ; CSR aggregate into B
    k_prep<<<nb128, 256>>>(A, 0, Wself0, bself0, bases0, B, Z);
    k_edges_csr<<<(N_NODES + 3) / 4, 256>>>(row, cnt, elist, coeffs0, Z, B);

    // layer 1: A = relu(B)@Wself1+b ; Z = relu(B)@bases1 ; CSR aggregate into A
    k_prep<<<nb128, 256>>>(B, 1, Wself1, bself1, bases1, A, Z);
    k_edges_csr<<<(N_NODES + 3) / 4, 256>>>(row, cnt, elist, coeffs1, Z, A);

    // readout: graph_emb = out[0:128]
    k_pool1<<<256, 256>>>(A);
    k_pool2<<<1, 128>>>(Wr1, br1, Wr2, br2, out, 256);

    // node_emb = out[128:]
    k_nodeemb<<<nb128, 256>>>(A, Wnp, bnp, out + EMB);
}

// round 10
// speedup vs baseline: 1.3088x; 1.2326x over previous
#include <cuda_runtime.h>

#define N_NODES 100000
#define N_EDGES 1000000
#define F_IN 15
#define H 64
#define EMB 128
#define NREL 13
#define NB 4

// ---------------- scratch (no allocations allowed) ----------------
__device__ float g_A[N_NODES * H];          // 25.6 MB  (h buffers)
__device__ float g_B[N_NODES * H];          // 25.6 MB
__device__ float g_M[N_NODES * H * NB];     // 102.4 MB (pre-aggregated basis sums)
__device__ float g_psum[256 * H];
__device__ float g_pmax[256 * H];
__device__ int   g_cnt[N_NODES];
__device__ int   g_row[N_NODES];
__device__ int   g_cur[N_NODES];
__device__ int   g_elist[N_EDGES];          // packed: src | (etype<<17)

// ---------------- CSR build ----------------
__global__ void k_zero(int* __restrict__ cnt) {
    int i = blockIdx.x * 256 + threadIdx.x;
    if (i < N_NODES) cnt[i] = 0;
}

__global__ void k_hist(const int* __restrict__ tgt, int* __restrict__ cnt) {
    int e = blockIdx.x * 256 + threadIdx.x;
    if (e < N_EDGES) atomicAdd(&cnt[tgt[e]], 1);
}

__global__ void k_scan(const int* __restrict__ cnt, int* __restrict__ row,
                       int* __restrict__ cur) {
    const int CH = (N_NODES + 1023) / 1024;
    __shared__ int sp[1024];
    int tid = threadIdx.x;
    int start = tid * CH;
    int s = 0;
    for (int i = 0; i < CH; i++) {
        int idx = start + i;
        if (idx < N_NODES) s += cnt[idx];
    }
    sp[tid] = s;
    __syncthreads();
    for (int off = 1; off < 1024; off <<= 1) {
        int v = 0;
        if (tid >= off) v = sp[tid - off];
        __syncthreads();
        if (tid >= off) sp[tid] += v;
        __syncthreads();
    }
    int run = (tid == 0) ? 0 : sp[tid - 1];
    for (int i = 0; i < CH; i++) {
        int idx = start + i;
        if (idx < N_NODES) {
            row[idx] = run;
            cur[idx] = run;
            run += cnt[idx];
        }
    }
}

__global__ void k_scatter(const int* __restrict__ src, const int* __restrict__ tgt,
                          const int* __restrict__ et, int* __restrict__ cur,
                          int* __restrict__ elist) {
    int e = blockIdx.x * 256 + threadIdx.x;
    if (e >= N_EDGES) return;
    int t = tgt[e];
    int pos = atomicAdd(&cur[t], 1);
    elist[pos] = src[e] | (et[e] << 17);
}

// ---------------- input projection: h0 = nf @ W_in + b_in ----------------
__global__ void k_inproj(const float* __restrict__ nf, const float* __restrict__ W,
                         const float* __restrict__ b, float* __restrict__ out) {
    __shared__ float sW[F_IN * H];
    __shared__ float sb[H];
    __shared__ float snf[4 * F_IN];
    int tid = threadIdx.x;
    for (int i = tid; i < F_IN * H; i += 256) sW[i] = W[i];
    if (tid < H) sb[tid] = b[tid];
    int n0 = blockIdx.x * 4;
    if (tid < 4 * F_IN) {
        int g = n0 * F_IN + tid;
        snf[tid] = (g < N_NODES * F_IN) ? nf[g] : 0.f;
    }
    __syncthreads();
    int lr = tid >> 6, col = tid & 63;
    int node = n0 + lr;
    if (node < N_NODES) {
        float acc = sb[col];
#pragma unroll
        for (int k = 0; k < F_IN; k++) acc = fmaf(snf[lr * F_IN + k], sW[k * H + col], acc);
        out[node * H + col] = acc;
    }
}

// ---------------- pre-aggregation over edges ----------------
// m[t, b, :] = sum_{e in in(t)} coeffs[etype(e), b] * act(h[src(e), :])
__global__ void k_edges_pre(const int* __restrict__ row, const int* __restrict__ cnt,
                            const int* __restrict__ elist, const float* __restrict__ coeffs,
                            const float* __restrict__ h, int relu_in,
                            float* __restrict__ m) {
    __shared__ float sc[NREL * NB];
    int tid = threadIdx.x;
    if (tid < NREL * NB) sc[tid] = coeffs[tid];
    __syncthreads();

    int lane = tid & 63;
    int t = blockIdx.x * 4 + (tid >> 6);
    if (t >= N_NODES) return;
    int beg = __ldg(&row[t]);
    int deg = __ldg(&cnt[t]);

    float a0[NB] = {0.f, 0.f, 0.f, 0.f};
    float a1[NB] = {0.f, 0.f, 0.f, 0.f};
    int i = 0;
    for (; i + 2 <= deg; i += 2) {
        int pkA = __ldg(&elist[beg + i]);
        int pkB = __ldg(&elist[beg + i + 1]);
        int sA = pkA & 0x1FFFF, rA = pkA >> 17;
        int sB = pkB & 0x1FFFF, rB = pkB >> 17;
        float vA = __ldg(&h[sA * H + lane]);
        float vB = __ldg(&h[sB * H + lane]);
        if (relu_in) { vA = fmaxf(vA, 0.f); vB = fmaxf(vB, 0.f); }
        const float* cA = sc + rA * NB;
        const float* cB = sc + rB * NB;
#pragma unroll
        for (int b = 0; b < NB; b++) {
            a0[b] = fmaf(cA[b], vA, a0[b]);
            a1[b] = fmaf(cB[b], vB, a1[b]);
        }
    }
    if (i < deg) {
        int pk = __ldg(&elist[beg + i]);
        int s = pk & 0x1FFFF, r = pk >> 17;
        float v = __ldg(&h[s * H + lane]);
        if (relu_in) v = fmaxf(v, 0.f);
        const float* cf = sc + r * NB;
#pragma unroll
        for (int b = 0; b < NB; b++) a0[b] = fmaf(cf[b], v, a0[b]);
    }
    float* mt = m + (size_t)t * (H * NB);
#pragma unroll
    for (int b = 0; b < NB; b++) mt[b * H + lane] = a0[b] + a1[b];
}

// ---------------- fused layer GEMM ----------------
// out = act(hin) @ Wself + bself + sum_b m[:,b,:] @ bases[b]
// 128-node tile, 8x4 microtile, K accumulated over 5 chunks of 64.
__global__ void k_layer(const float* __restrict__ hin, int relu_in,
                        const float* __restrict__ m,
                        const float* __restrict__ Wself, const float* __restrict__ bself,
                        const float* __restrict__ bases,
                        float* __restrict__ out) {
    __shared__ float sA[H][132];   // transposed: sA[k][row], 128 rows
    __shared__ float sB[H][68];    // sB[k][col]
    int tid = threadIdx.x;         // 256
    int n0 = blockIdx.x * 128;

    int tx = tid & 15, ty = tid >> 4;
    float c[8][4] = {};

    for (int ch = 0; ch < 5; ch++) {
        // load A-panel chunk (transposed)
        if (ch == 0) {
            for (int i = tid; i < 128 * H; i += 256) {
                int r = i >> 6, k = i & 63;
                int node = n0 + r;
                float v = (node < N_NODES) ? hin[node * H + k] : 0.f;
                if (relu_in) v = fmaxf(v, 0.f);
                sA[k][r] = v;
            }
        } else {
            const float* msrc = m + (ch - 1) * H;
            for (int i = tid; i < 128 * H; i += 256) {
                int r = i >> 6, k = i & 63;
                int node = n0 + r;
                sA[k][r] = (node < N_NODES) ? msrc[(size_t)node * (H * NB) + k] : 0.f;
            }
        }
        // load B-panel chunk
        const float* Bsrc = (ch == 0) ? Wself : (bases + (ch - 1) * H * H);
        for (int i = tid; i < H * H; i += 256) sB[i >> 6][i & 63] = Bsrc[i];
        __syncthreads();

#pragma unroll 8
        for (int k = 0; k < H; k++) {
            float4 a0 = *(const float4*)&sA[k][ty * 8];
            float4 a1 = *(const float4*)&sA[k][ty * 8 + 4];
            float4 b4 = *(const float4*)&sB[k][tx * 4];
            float av[8] = {a0.x, a0.y, a0.z, a0.w, a1.x, a1.y, a1.z, a1.w};
            float bv[4] = {b4.x, b4.y, b4.z, b4.w};
#pragma unroll
            for (int i = 0; i < 8; i++)
#pragma unroll
                for (int j = 0; j < 4; j++)
                    c[i][j] = fmaf(av[i], bv[j], c[i][j]);
        }
        __syncthreads();
    }

    int colbase = tx * 4;
    float4 bsv = *(const float4*)&bself[colbase];
#pragma unroll
    for (int i = 0; i < 8; i++) {
        int node = n0 + ty * 8 + i;
        if (node < N_NODES) {
            float4 o = {c[i][0] + bsv.x, c[i][1] + bsv.y,
                        c[i][2] + bsv.z, c[i][3] + bsv.w};
            *(float4*)&out[node * H + colbase] = o;
        }
    }
}

// ---------------- pooling stage 1 ----------------
__global__ void k_pool1(const float* __restrict__ hbuf) {
    int tid = threadIdx.x;
    int col = tid & 63;
    int sub = tid >> 6;
    float s = 0.f, mx = -3.4e38f;
    for (int n = blockIdx.x * 4 + sub; n < N_NODES; n += gridDim.x * 4) {
        float v = fmaxf(hbuf[n * H + col], 0.f);
        s += v;
        mx = fmaxf(mx, v);
    }
    __shared__ float ss[256], sm[256];
    ss[tid] = s; sm[tid] = mx;
    __syncthreads();
    if (sub == 0) {
        float fs = ss[col] + ss[64 + col] + ss[128 + col] + ss[192 + col];
        float fm = fmaxf(fmaxf(sm[col], sm[64 + col]), fmaxf(sm[128 + col], sm[192 + col]));
        g_psum[blockIdx.x * H + col] = fs;
        g_pmax[blockIdx.x * H + col] = fm;
    }
}

// ---------------- pooling stage 2 + readout MLP ----------------
__global__ void k_pool2(const float* __restrict__ Wr1, const float* __restrict__ br1,
                        const float* __restrict__ Wr2, const float* __restrict__ br2,
                        float* __restrict__ out, int nblocks) {
    __shared__ float g[2 * H];
    __shared__ float t[H];
    int tid = threadIdx.x;
    if (tid < H) {
        float s = 0.f, mx = -3.4e38f;
        for (int b = 0; b < nblocks; b++) {
            s += g_psum[b * H + tid];
            mx = fmaxf(mx, g_pmax[b * H + tid]);
        }
        g[tid] = s / (float)N_NODES;
        g[H + tid] = mx;
    }
    __syncthreads();
    if (tid < H) {
        float a = br1[tid];
#pragma unroll 8
        for (int i = 0; i < 2 * H; i++) a = fmaf(g[i], Wr1[i * H + tid], a);
        t[tid] = fmaxf(a, 0.f);
    }
    __syncthreads();
    if (tid < EMB) {
        float a = br2[tid];
#pragma unroll 8
        for (int j = 0; j < H; j++) a = fmaf(t[j], Wr2[j * EMB + tid], a);
        out[tid] = a;
    }
}

// ---------------- node embedding (128-node tile, 8x4 microtile) ----------------
__global__ void k_nodeemb(const float* __restrict__ hbuf, const float* __restrict__ Wnp,
                          const float* __restrict__ bnp, float* __restrict__ out) {
    __shared__ float sA[H][132];
    __shared__ float sB[H][68];
    int tid = threadIdx.x;
    int n0 = blockIdx.x * 128;

    for (int i = tid; i < 128 * H; i += 256) {
        int row = i >> 6, k = i & 63;
        int node = n0 + row;
        sA[k][row] = (node < N_NODES) ? fmaxf(hbuf[node * H + k], 0.f) : 0.f;
    }

    int tx = tid & 15, ty = tid >> 4;

    for (int m = 0; m < 2; m++) {
        for (int i = tid; i < H * H; i += 256) {
            int k = i >> 6, col = i & 63;
            sB[k][col] = Wnp[k * EMB + m * H + col];
        }
        __syncthreads();

        float c[8][4] = {};
#pragma unroll 8
        for (int k = 0; k < H; k++) {
            float4 a0 = *(const float4*)&sA[k][ty * 8];
            float4 a1 = *(const float4*)&sA[k][ty * 8 + 4];
            float4 b4 = *(const float4*)&sB[k][tx * 4];
            float av[8] = {a0.x, a0.y, a0.z, a0.w, a1.x, a1.y, a1.z, a1.w};
            float bv[4] = {b4.x, b4.y, b4.z, b4.w};
#pragma unroll
            for (int i = 0; i < 8; i++)
#pragma unroll
                for (int j = 0; j < 4; j++)
                    c[i][j] = fmaf(av[i], bv[j], c[i][j]);
        }

        int colbase = tx * 4;
        float4 bv4 = *(const float4*)&bnp[m * H + colbase];
#pragma unroll
        for (int i = 0; i < 8; i++) {
            int node = n0 + ty * 8 + i;
            if (node < N_NODES) {
                float4 o = {c[i][0] + bv4.x, c[i][1] + bv4.y,
                            c[i][2] + bv4.z, c[i][3] + bv4.w};
                *(float4*)&out[node * EMB + m * H + colbase] = o;
            }
        }
        __syncthreads();
    }
}

// ---------------- launch ----------------
extern "C" void kernel_launch(void* const* d_in, const int* in_sizes, int n_in,
                              void* d_out, int out_size) {
    const float* nf     = (const float*)d_in[0];
    const int*   ei     = (const int*)  d_in[1];
    const int*   et     = (const int*)  d_in[2];
    const float* W_in   = (const float*)d_in[3];
    const float* b_in   = (const float*)d_in[4];
    const float* Wself0 = (const float*)d_in[5];
    const float* bself0 = (const float*)d_in[6];
    const float* bases0 = (const float*)d_in[7];
    const float* coeffs0= (const float*)d_in[8];
    const float* Wself1 = (const float*)d_in[9];
    const float* bself1 = (const float*)d_in[10];
    const float* bases1 = (const float*)d_in[11];
    const float* coeffs1= (const float*)d_in[12];
    const float* Wr1    = (const float*)d_in[13];
    const float* br1    = (const float*)d_in[14];
    const float* Wr2    = (const float*)d_in[15];
    const float* br2    = (const float*)d_in[16];
    const float* Wnp    = (const float*)d_in[17];
    const float* bnp    = (const float*)d_in[18];
    float* out = (float*)d_out;

    float *A, *B, *M;
    int *cnt, *row, *cur, *elist;
    cudaGetSymbolAddress((void**)&A, g_A);
    cudaGetSymbolAddress((void**)&B, g_B);
    cudaGetSymbolAddress((void**)&M, g_M);
    cudaGetSymbolAddress((void**)&cnt, g_cnt);
    cudaGetSymbolAddress((void**)&row, g_row);
    cudaGetSymbolAddress((void**)&cur, g_cur);
    cudaGetSymbolAddress((void**)&elist, g_elist);

    const int* src = ei;
    const int* tgt = ei + N_EDGES;

    int nb128 = (N_NODES + 127) / 128;
    int nbN   = (N_NODES + 255) / 256;
    int nbE   = (N_EDGES + 255) / 256;
    int nbT4  = (N_NODES + 3) / 4;

    // CSR build (by target)
    k_zero<<<nbN, 256>>>(cnt);
    k_hist<<<nbE, 256>>>(tgt, cnt);
    k_scan<<<1, 1024>>>(cnt, row, cur);
    k_scatter<<<nbE, 256>>>(src, tgt, et, cur, elist);

    // h0 = nf @ W_in + b_in -> A
    k_inproj<<<nbT4, 256>>>(nf, W_in, b_in, A);

    // layer 0: pre-aggregate h0 into M, then fused GEMM -> B
    k_edges_pre<<<nbT4, 256>>>(row, cnt, elist, coeffs0, A, 0, M);
    k_layer<<<nb128, 256>>>(A, 0, M, Wself0, bself0, bases0, B);

    // layer 1: pre-aggregate relu(h1) into M, then fused GEMM -> A
    k_edges_pre<<<nbT4, 256>>>(row, cnt, elist, coeffs1, B, 1, M);
    k_layer<<<nb128, 256>>>(B, 1, M, Wself1, bself1, bases1, A);

    // readout: graph_emb = out[0:128]
    k_pool1<<<256, 256>>>(A);
    k_pool2<<<1, 128>>>(Wr1, br1, Wr2, br2, out, 256);

    // node_emb = out[128:]
    k_nodeemb<<<nb128, 256>>>(A, Wnp, bnp, out + EMB);
}

// round 11
// speedup vs baseline: 1.3649x; 1.0428x over previous
#include <cuda_runtime.h>

#define N_NODES 100000
#define N_EDGES 1000000
#define F_IN 15
#define H 64
#define EMB 128
#define NREL 13
#define NB 4

typedef unsigned long long u64;

// packed-f32x2 helpers (sm_100+ PTX; ptxas never emits FFMA2 from C++)
__device__ __forceinline__ u64 bcast2(float x) {
    unsigned u = __float_as_uint(x);
    u64 r;
    asm("mov.b64 %0, {%1, %1};" : "=l"(r) : "r"(u));
    return r;
}
__device__ __forceinline__ void fma2(u64& c, u64 a, u64 b) {
    asm("fma.rn.f32x2 %0, %1, %2, %3;" : "=l"(c) : "l"(a), "l"(b), "l"(c));
}
__device__ __forceinline__ void unpack2(u64 v, float& lo, float& hi) {
    unsigned l, h;
    asm("mov.b64 {%0, %1}, %2;" : "=r"(l), "=r"(h) : "l"(v));
    lo = __uint_as_float(l);
    hi = __uint_as_float(h);
}

// ---------------- scratch (no allocations allowed) ----------------
__device__ float g_A[N_NODES * H];          // 25.6 MB  (h buffers)
__device__ float g_B[N_NODES * H];          // 25.6 MB
__device__ float g_M[N_NODES * H * NB];     // 102.4 MB (pre-aggregated basis sums)
__device__ float g_psum[256 * H];
__device__ float g_pmax[256 * H];
__device__ int   g_cnt[N_NODES];
__device__ int   g_row[N_NODES];
__device__ int   g_cur[N_NODES];
__device__ int   g_elist[N_EDGES];          // packed: src | (etype<<17)

// ---------------- CSR build ----------------
__global__ void k_zero(int* __restrict__ cnt) {
    int i = blockIdx.x * 256 + threadIdx.x;
    if (i < N_NODES) cnt[i] = 0;
}

__global__ void k_hist(const int* __restrict__ tgt, int* __restrict__ cnt) {
    int e = blockIdx.x * 256 + threadIdx.x;
    if (e < N_EDGES) atomicAdd(&cnt[tgt[e]], 1);
}

__global__ void k_scan(const int* __restrict__ cnt, int* __restrict__ row,
                       int* __restrict__ cur) {
    const int CH = (N_NODES + 1023) / 1024;
    __shared__ int sp[1024];
    int tid = threadIdx.x;
    int start = tid * CH;
    int s = 0;
    for (int i = 0; i < CH; i++) {
        int idx = start + i;
        if (idx < N_NODES) s += cnt[idx];
    }
    sp[tid] = s;
    __syncthreads();
    for (int off = 1; off < 1024; off <<= 1) {
        int v = 0;
        if (tid >= off) v = sp[tid - off];
        __syncthreads();
        if (tid >= off) sp[tid] += v;
        __syncthreads();
    }
    int run = (tid == 0) ? 0 : sp[tid - 1];
    for (int i = 0; i < CH; i++) {
        int idx = start + i;
        if (idx < N_NODES) {
            row[idx] = run;
            cur[idx] = run;
            run += cnt[idx];
        }
    }
}

__global__ void k_scatter(const int* __restrict__ src, const int* __restrict__ tgt,
                          const int* __restrict__ et, int* __restrict__ cur,
                          int* __restrict__ elist) {
    int e = blockIdx.x * 256 + threadIdx.x;
    if (e >= N_EDGES) return;
    int t = tgt[e];
    int pos = atomicAdd(&cur[t], 1);
    elist[pos] = src[e] | (et[e] << 17);
}

// ---------------- input projection: h0 = nf @ W_in + b_in ----------------
__global__ void k_inproj(const float* __restrict__ nf, const float* __restrict__ W,
                         const float* __restrict__ b, float* __restrict__ out) {
    __shared__ float sW[F_IN * H];
    __shared__ float sb[H];
    __shared__ float snf[4 * F_IN];
    int tid = threadIdx.x;
    for (int i = tid; i < F_IN * H; i += 256) sW[i] = W[i];
    if (tid < H) sb[tid] = b[tid];
    int n0 = blockIdx.x * 4;
    if (tid < 4 * F_IN) {
        int g = n0 * F_IN + tid;
        snf[tid] = (g < N_NODES * F_IN) ? nf[g] : 0.f;
    }
    __syncthreads();
    int lr = tid >> 6, col = tid & 63;
    int node = n0 + lr;
    if (node < N_NODES) {
        float acc = sb[col];
#pragma unroll
        for (int k = 0; k < F_IN; k++) acc = fmaf(snf[lr * F_IN + k], sW[k * H + col], acc);
        out[node * H + col] = acc;
    }
}

// ---------------- pre-aggregation over edges ----------------
// m[t, b, :] = sum_{e in in(t)} coeffs[etype(e), b] * act(h[src(e), :])
__global__ void k_edges_pre(const int* __restrict__ row, const int* __restrict__ cnt,
                            const int* __restrict__ elist, const float* __restrict__ coeffs,
                            const float* __restrict__ h, int relu_in,
                            float* __restrict__ m) {
    __shared__ float sc[NREL * NB];
    int tid = threadIdx.x;
    if (tid < NREL * NB) sc[tid] = coeffs[tid];
    __syncthreads();

    int lane = tid & 63;
    int t = blockIdx.x * 4 + (tid >> 6);
    if (t >= N_NODES) return;
    int beg = __ldg(&row[t]);
    int deg = __ldg(&cnt[t]);

    float a0[NB] = {0.f, 0.f, 0.f, 0.f};
    float a1[NB] = {0.f, 0.f, 0.f, 0.f};
    int i = 0;
    for (; i + 2 <= deg; i += 2) {
        int pkA = __ldg(&elist[beg + i]);
        int pkB = __ldg(&elist[beg + i + 1]);
        int sA = pkA & 0x1FFFF, rA = pkA >> 17;
        int sB = pkB & 0x1FFFF, rB = pkB >> 17;
        float vA = __ldg(&h[sA * H + lane]);
        float vB = __ldg(&h[sB * H + lane]);
        if (relu_in) { vA = fmaxf(vA, 0.f); vB = fmaxf(vB, 0.f); }
        const float* cA = sc + rA * NB;
        const float* cB = sc + rB * NB;
#pragma unroll
        for (int b = 0; b < NB; b++) {
            a0[b] = fmaf(cA[b], vA, a0[b]);
            a1[b] = fmaf(cB[b], vB, a1[b]);
        }
    }
    if (i < deg) {
        int pk = __ldg(&elist[beg + i]);
        int s = pk & 0x1FFFF, r = pk >> 17;
        float v = __ldg(&h[s * H + lane]);
        if (relu_in) v = fmaxf(v, 0.f);
        const float* cf = sc + r * NB;
#pragma unroll
        for (int b = 0; b < NB; b++) a0[b] = fmaf(cf[b], v, a0[b]);
    }
    float* mt = m + (size_t)t * (H * NB);
#pragma unroll
    for (int b = 0; b < NB; b++) mt[b * H + lane] = a0[b] + a1[b];
}

// ---------------- fused layer GEMM (f32x2 packed FMAs) ----------------
// out = act(hin) @ Wself + bself + sum_b m[:,b,:] @ bases[b]
// 128-node tile; each thread: 8 rows (as 4 packed row-pairs) x 4 cols.
__global__ void k_layer(const float* __restrict__ hin, int relu_in,
                        const float* __restrict__ m,
                        const float* __restrict__ Wself, const float* __restrict__ bself,
                        const float* __restrict__ bases,
                        float* __restrict__ out) {
    __shared__ float sA[H][132];   // transposed: sA[k][row], 128 rows (row-stride 528B, 16B-aligned)
    __shared__ float sB[H][68];    // sB[k][col]
    int tid = threadIdx.x;         // 256
    int n0 = blockIdx.x * 128;

    int tx = tid & 15, ty = tid >> 4;
    u64 c2[4][4] = {};             // row-pairs (2p,2p+1) x 4 cols

    for (int ch = 0; ch < 5; ch++) {
        if (ch == 0) {
            for (int i = tid; i < 128 * H; i += 256) {
                int r = i >> 6, k = i & 63;
                int node = n0 + r;
                float v = (node < N_NODES) ? hin[node * H + k] : 0.f;
                if (relu_in) v = fmaxf(v, 0.f);
                sA[k][r] = v;
            }
        } else {
            const float* msrc = m + (ch - 1) * H;
            for (int i = tid; i < 128 * H; i += 256) {
                int r = i >> 6, k = i & 63;
                int node = n0 + r;
                sA[k][r] = (node < N_NODES) ? msrc[(size_t)node * (H * NB) + k] : 0.f;
            }
        }
        const float* Bsrc = (ch == 0) ? Wself : (bases + (ch - 1) * H * H);
        for (int i = tid; i < H * H; i += 256) sB[i >> 6][i & 63] = Bsrc[i];
        __syncthreads();

#pragma unroll 8
        for (int k = 0; k < H; k++) {
            // adjacent rows are already packed pairs in smem
            ulonglong2 aA = *(const ulonglong2*)&sA[k][ty * 8];      // pairs (0,1),(2,3)
            ulonglong2 aB = *(const ulonglong2*)&sA[k][ty * 8 + 4];  // pairs (4,5),(6,7)
            float4 b4 = *(const float4*)&sB[k][tx * 4];
            u64 ap[4] = {aA.x, aA.y, aB.x, aB.y};
            u64 bb[4] = {bcast2(b4.x), bcast2(b4.y), bcast2(b4.z), bcast2(b4.w)};
#pragma unroll
            for (int p = 0; p < 4; p++) {
#pragma unroll
                for (int j = 0; j < 4; j++)
                    fma2(c2[p][j], ap[p], bb[j]);
            }
        }
        __syncthreads();
    }

    int colbase = tx * 4;
    float4 bsv = *(const float4*)&bself[colbase];
    float bias[4] = {bsv.x, bsv.y, bsv.z, bsv.w};
#pragma unroll
    for (int p = 0; p < 4; p++) {
        float lo[4], hi[4];
#pragma unroll
        for (int j = 0; j < 4; j++) unpack2(c2[p][j], lo[j], hi[j]);
        int node0 = n0 + ty * 8 + 2 * p;
        if (node0 < N_NODES) {
            float4 o = {lo[0] + bias[0], lo[1] + bias[1], lo[2] + bias[2], lo[3] + bias[3]};
            *(float4*)&out[node0 * H + colbase] = o;
        }
        if (node0 + 1 < N_NODES) {
            float4 o = {hi[0] + bias[0], hi[1] + bias[1], hi[2] + bias[2], hi[3] + bias[3]};
            *(float4*)&out[(node0 + 1) * H + colbase] = o;
        }
    }
}

// ---------------- pooling stage 1 ----------------
__global__ void k_pool1(const float* __restrict__ hbuf) {
    int tid = threadIdx.x;
    int col = tid & 63;
    int sub = tid >> 6;
    float s = 0.f, mx = -3.4e38f;
    for (int n = blockIdx.x * 4 + sub; n < N_NODES; n += gridDim.x * 4) {
        float v = fmaxf(hbuf[n * H + col], 0.f);
        s += v;
        mx = fmaxf(mx, v);
    }
    __shared__ float ss[256], sm[256];
    ss[tid] = s; sm[tid] = mx;
    __syncthreads();
    if (sub == 0) {
        float fs = ss[col] + ss[64 + col] + ss[128 + col] + ss[192 + col];
        float fm = fmaxf(fmaxf(sm[col], sm[64 + col]), fmaxf(sm[128 + col], sm[192 + col]));
        g_psum[blockIdx.x * H + col] = fs;
        g_pmax[blockIdx.x * H + col] = fm;
    }
}

// ---------------- pooling stage 2 + readout MLP ----------------
__global__ void k_pool2(const float* __restrict__ Wr1, const float* __restrict__ br1,
                        const float* __restrict__ Wr2, const float* __restrict__ br2,
                        float* __restrict__ out, int nblocks) {
    __shared__ float g[2 * H];
    __shared__ float t[H];
    int tid = threadIdx.x;
    if (tid < H) {
        float s = 0.f, mx = -3.4e38f;
        for (int b = 0; b < nblocks; b++) {
            s += g_psum[b * H + tid];
            mx = fmaxf(mx, g_pmax[b * H + tid]);
        }
        g[tid] = s / (float)N_NODES;
        g[H + tid] = mx;
    }
    __syncthreads();
    if (tid < H) {
        float a = br1[tid];
#pragma unroll 8
        for (int i = 0; i < 2 * H; i++) a = fmaf(g[i], Wr1[i * H + tid], a);
        t[tid] = fmaxf(a, 0.f);
    }
    __syncthreads();
    if (tid < EMB) {
        float a = br2[tid];
#pragma unroll 8
        for (int j = 0; j < H; j++) a = fmaf(t[j], Wr2[j * EMB + tid], a);
        out[tid] = a;
    }
}

// ---------------- node embedding (f32x2 packed FMAs) ----------------
__global__ void k_nodeemb(const float* __restrict__ hbuf, const float* __restrict__ Wnp,
                          const float* __restrict__ bnp, float* __restrict__ out) {
    __shared__ float sA[H][132];
    __shared__ float sB[H][68];
    int tid = threadIdx.x;
    int n0 = blockIdx.x * 128;

    for (int i = tid; i < 128 * H; i += 256) {
        int row = i >> 6, k = i & 63;
        int node = n0 + row;
        sA[k][row] = (node < N_NODES) ? fmaxf(hbuf[node * H + k], 0.f) : 0.f;
    }

    int tx = tid & 15, ty = tid >> 4;

    for (int m = 0; m < 2; m++) {
        for (int i = tid; i < H * H; i += 256) {
            int k = i >> 6, col = i & 63;
            sB[k][col] = Wnp[k * EMB + m * H + col];
        }
        __syncthreads();

        u64 c2[4][4] = {};
#pragma unroll 8
        for (int k = 0; k < H; k++) {
            ulonglong2 aA = *(const ulonglong2*)&sA[k][ty * 8];
            ulonglong2 aB = *(const ulonglong2*)&sA[k][ty * 8 + 4];
            float4 b4 = *(const float4*)&sB[k][tx * 4];
            u64 ap[4] = {aA.x, aA.y, aB.x, aB.y};
            u64 bb[4] = {bcast2(b4.x), bcast2(b4.y), bcast2(b4.z), bcast2(b4.w)};
#pragma unroll
            for (int p = 0; p < 4; p++) {
#pragma unroll
                for (int j = 0; j < 4; j++)
                    fma2(c2[p][j], ap[p], bb[j]);
            }
        }

        int colbase = tx * 4;
        float4 bv4 = *(const float4*)&bnp[m * H + colbase];
        float bias[4] = {bv4.x, bv4.y, bv4.z, bv4.w};
#pragma unroll
        for (int p = 0; p < 4; p++) {
            float lo[4], hi[4];
#pragma unroll
            for (int j = 0; j < 4; j++) unpack2(c2[p][j], lo[j], hi[j]);
            int node0 = n0 + ty * 8 + 2 * p;
            if (node0 < N_NODES) {
                float4 o = {lo[0] + bias[0], lo[1] + bias[1], lo[2] + bias[2], lo[3] + bias[3]};
                *(float4*)&out[node0 * EMB + m * H + colbase] = o;
            }
            if (node0 + 1 < N_NODES) {
                float4 o = {hi[0] + bias[0], hi[1] + bias[1], hi[2] + bias[2], hi[3] + bias[3]};
                *(float4*)&out[(node0 + 1) * EMB + m * H + colbase] = o;
            }
        }
        __syncthreads();
    }
}

// ---------------- launch ----------------
extern "C" void kernel_launch(void* const* d_in, const int* in_sizes, int n_in,
                              void* d_out, int out_size) {
    const float* nf     = (const float*)d_in[0];
    const int*   ei     = (const int*)  d_in[1];
    const int*   et     = (const int*)  d_in[2];
    const float* W_in   = (const float*)d_in[3];
    const float* b_in   = (const float*)d_in[4];
    const float* Wself0 = (const float*)d_in[5];
    const float* bself0 = (const float*)d_in[6];
    const float* bases0 = (const float*)d_in[7];
    const float* coeffs0= (const float*)d_in[8];
    const float* Wself1 = (const float*)d_in[9];
    const float* bself1 = (const float*)d_in[10];
    const float* bases1 = (const float*)d_in[11];
    const float* coeffs1= (const float*)d_in[12];
    const float* Wr1    = (const float*)d_in[13];
    const float* br1    = (const float*)d_in[14];
    const float* Wr2    = (const float*)d_in[15];
    const float* br2    = (const float*)d_in[16];
    const float* Wnp    = (const float*)d_in[17];
    const float* bnp    = (const float*)d_in[18];
    float* out = (float*)d_out;

    float *A, *B, *M;
    int *cnt, *row, *cur, *elist;
    cudaGetSymbolAddress((void**)&A, g_A);
    cudaGetSymbolAddress((void**)&B, g_B);
    cudaGetSymbolAddress((void**)&M, g_M);
    cudaGetSymbolAddress((void**)&cnt, g_cnt);
    cudaGetSymbolAddress((void**)&row, g_row);
    cudaGetSymbolAddress((void**)&cur, g_cur);
    cudaGetSymbolAddress((void**)&elist, g_elist);

    const int* src = ei;
    const int* tgt = ei + N_EDGES;

    int nb128 = (N_NODES + 127) / 128;
    int nbN   = (N_NODES + 255) / 256;
    int nbE   = (N_EDGES + 255) / 256;
    int nbT4  = (N_NODES + 3) / 4;

    // CSR build (by target)
    k_zero<<<nbN, 256>>>(cnt);
    k_hist<<<nbE, 256>>>(tgt, cnt);
    k_scan<<<1, 1024>>>(cnt, row, cur);
    k_scatter<<<nbE, 256>>>(src, tgt, et, cur, elist);

    // h0 = nf @ W_in + b_in -> A
    k_inproj<<<nbT4, 256>>>(nf, W_in, b_in, A);

    // layer 0: pre-aggregate h0 into M, then fused GEMM -> B
    k_edges_pre<<<nbT4, 256>>>(row, cnt, elist, coeffs0, A, 0, M);
    k_layer<<<nb128, 256>>>(A, 0, M, Wself0, bself0, bases0, B);

    // layer 1: pre-aggregate relu(h1) into M, then fused GEMM -> A
    k_edges_pre<<<nbT4, 256>>>(row, cnt, elist, coeffs1, B, 1, M);
    k_layer<<<nb128, 256>>>(B, 1, M, Wself1, bself1, bases1, A);

    // readout: graph_emb = out[0:128]
    k_pool1<<<256, 256>>>(A);
    k_pool2<<<1, 128>>>(Wr1, br1, Wr2, br2, out, 256);

    // node_emb = out[128:]
    k_nodeemb<<<nb128, 256>>>(A, Wnp, bnp, out + EMB);
}